// round 8
// baseline (speedup 1.0000x reference)
#include <cuda_runtime.h>

#define NN 50000
#define NE 800000
#define DI 128
#define DH 128
#define DO 64
#define SPAD 132    // padded smem row stride (floats) for gemm tiles
#define APAD 66     // smem stride for fused-gather mean tile

// Scratch (device globals). 16B-aligned for float4 access.
__device__ __align__(16) float g_agg[NN * DI];   // layer-1 mean features
__device__ __align__(16) float g_h[NN * DH];     // layer-1 output
__device__ __align__(16) float g_p[NN * DO];     // h @ Wl2^T (pre-aggregation)
__device__ int g_rp[NN + 1];                     // CSR row ptr (by dst)
__device__ int g_cur[NN];                        // degree, then cursor
__device__ int g_srt[NE];                        // src ids sorted by dst
__device__ int g_blksum[256];                    // scan partials
__device__ int g_ei_is32;

// ---------------- packed fp32x2 helpers ----------------
__device__ __forceinline__ void fma2(unsigned long long &d, unsigned long long a, unsigned long long b) {
    asm("fma.rn.f32x2 %0, %1, %2, %0;" : "+l"(d) : "l"(a), "l"(b));
}
__device__ __forceinline__ float2 unpack2(unsigned long long v) {
    float2 r;
    asm("mov.b64 {%0, %1}, %2;" : "=f"(r.x), "=f"(r.y) : "l"(v));
    return r;
}

__device__ __forceinline__ void load_edge(const void* ei, int e, int is32, int& src, int& dst) {
    if (is32) {
        const int* p = (const int*)ei;
        src = p[e]; dst = p[NE + e];
    } else {
        const long long* p = (const long long*)ei;
        src = (int)p[e]; dst = (int)p[NE + e];
    }
}

// ---------------- init: zero degrees + edge-index dtype probe ----------------
__global__ void k_init(const void* ei) {
    int i = blockIdx.x * blockDim.x + threadIdx.x;
    if (i < NN) g_cur[i] = 0;
    if (blockIdx.x == 0 && threadIdx.x == 0) {
        const long long* p = (const long long*)ei;
        int is32 = 0;
        #pragma unroll 8
        for (int t = 0; t < 64; t++) {
            long long v = p[t];
            if (v < 0 || v >= NN) is32 = 1;
        }
        g_ei_is32 = is32;
    }
}

// ---------------- CSR build ----------------
__global__ void k_hist(const void* __restrict__ ei) {
    int e = blockIdx.x * blockDim.x + threadIdx.x;
    if (e >= NE) return;
    int src, dst;
    load_edge(ei, e, g_ei_is32, src, dst);
    if ((unsigned)src < NN && (unsigned)dst < NN) atomicAdd(&g_cur[dst], 1);
}
__global__ void k_scan1() {
    __shared__ int s[256];
    int tid = threadIdx.x;
    int i = blockIdx.x * 256 + tid;
    s[tid] = (i < NN) ? g_cur[i] : 0;
    __syncthreads();
    for (int o = 128; o > 0; o >>= 1) {
        if (tid < o) s[tid] += s[tid + o];
        __syncthreads();
    }
    if (tid == 0) g_blksum[blockIdx.x] = s[0];
}
__global__ void k_scan2(int nblk) {
    __shared__ int s[256];
    int tid = threadIdx.x;
    int v = (tid < nblk) ? g_blksum[tid] : 0;
    s[tid] = v;
    __syncthreads();
    for (int o = 1; o < 256; o <<= 1) {
        int t = (tid >= o) ? s[tid - o] : 0;
        __syncthreads();
        s[tid] += t;
        __syncthreads();
    }
    if (tid < nblk) g_blksum[tid] = s[tid] - v;
}
__global__ void k_scan3() {
    __shared__ int s[256];
    int tid = threadIdx.x;
    int i = blockIdx.x * 256 + tid;
    int v = (i < NN) ? g_cur[i] : 0;
    s[tid] = v;
    __syncthreads();
    for (int o = 1; o < 256; o <<= 1) {
        int t = (tid >= o) ? s[tid - o] : 0;
        __syncthreads();
        s[tid] += t;
        __syncthreads();
    }
    int excl = g_blksum[blockIdx.x] + s[tid] - v;
    if (i < NN) {
        g_rp[i]  = excl;
        g_cur[i] = excl;
        if (i == NN - 1) g_rp[NN] = excl + v;
    }
}
__global__ void k_reorder(const void* __restrict__ ei) {
    int e = blockIdx.x * blockDim.x + threadIdx.x;
    if (e >= NE) return;
    int src, dst;
    load_edge(ei, e, g_ei_is32, src, dst);
    if ((unsigned)src < NN && (unsigned)dst < NN) {
        int pos = atomicAdd(&g_cur[dst], 1);
        if (pos < NE) g_srt[pos] = src;
    }
}

// ---------------- gather (layer 1): mean of x[src] per dst -> g_agg ----------------
__global__ void k_gather_x(const float* __restrict__ x) {
    int n    = (blockIdx.x * blockDim.x + threadIdx.x) >> 5;
    int lane = threadIdx.x & 31;
    if (n >= NN) return;
    int beg = g_rp[n], end = g_rp[n + 1];
    float4 a = make_float4(0.f, 0.f, 0.f, 0.f);
    int i = beg;
    for (; i + 2 <= end; i += 2) {
        int s0 = g_srt[i], s1 = g_srt[i + 1];
        float4 v0 = *(const float4*)(x + (size_t)s0 * DI + lane * 4);
        float4 v1 = *(const float4*)(x + (size_t)s1 * DI + lane * 4);
        a.x += v0.x + v1.x; a.y += v0.y + v1.y;
        a.z += v0.z + v1.z; a.w += v0.w + v1.w;
    }
    if (i < end) {
        int s0 = g_srt[i];
        float4 v0 = *(const float4*)(x + (size_t)s0 * DI + lane * 4);
        a.x += v0.x; a.y += v0.y; a.z += v0.z; a.w += v0.w;
    }
    float inv = 1.0f / fmaxf((float)(end - beg), 1.0f);
    *(float4*)(g_agg + (size_t)n * DI + lane * 4) =
        make_float4(a.x * inv, a.y * inv, a.z * inv, a.w * inv);
}

// ---------------- layer-1 fused GEMM: h = relu(mean @ Wl1^T + bl1 + x @ Wr1^T) ----------------
// 512 threads, 64 nodes x 128 outputs; per thread 4x4; weight regs double-buffered.
__global__ void __launch_bounds__(512, 1) k_gemm1(
    const float* __restrict__ x, const float* __restrict__ Wl,
    const float* __restrict__ bl, const float* __restrict__ Wr)
{
    extern __shared__ float smem[];
    float* sWl = smem;                  // [128][SPAD]
    float* sWr = sWl + DH * SPAD;       // [128][SPAD]
    float* sXm = sWr + DH * SPAD;       // [64][SPAD]
    float* sXx = sXm + 64 * SPAD;       // [64][SPAD]

    const int tid   = threadIdx.x;
    const int node0 = blockIdx.x * 64;
    const int r     = tid >> 5;
    const int k4    = (tid & 31) * 4;

    #pragma unroll
    for (int it = 0; it < 8; it++) {
        int j = it * 16 + r;
        *(float4*)(sWl + j * SPAD + k4) = *(const float4*)(Wl + j * DI + k4);
        *(float4*)(sWr + j * SPAD + k4) = *(const float4*)(Wr + j * DI + k4);
    }
    #pragma unroll
    for (int it = 0; it < 4; it++) {
        int nl = it * 16 + r;
        int n  = node0 + nl;
        float4 xm = make_float4(0.f, 0.f, 0.f, 0.f), xx = xm;
        if (n < NN) {
            xm = *(const float4*)(g_agg + (size_t)n * DI + k4);
            xx = *(const float4*)(x + (size_t)n * DI + k4);
        }
        *(float4*)(sXm + nl * SPAD + k4) = xm;
        *(float4*)(sXx + nl * SPAD + k4) = xx;
    }
    __syncthreads();

    const int lane = tid & 31;
    const int jl   = lane & 15;
    const int jo   = (r >> 3) * 4;
    const int nb   = ((r & 7) * 2 + (lane >> 4)) * 4;

    unsigned long long acc[4][4];
    #pragma unroll
    for (int nn = 0; nn < 4; nn++)
        #pragma unroll
        for (int jj = 0; jj < 4; jj++) acc[nn][jj] = 0ull;

    // prime weight registers for k=0
    ulonglong2 wlc[4], wrc[4];
    #pragma unroll
    for (int jj = 0; jj < 4; jj++) {
        int j = jl + 16 * (jo + jj);
        wlc[jj] = *(const ulonglong2*)(sWl + j * SPAD);
        wrc[jj] = *(const ulonglong2*)(sWr + j * SPAD);
    }

    #pragma unroll 2
    for (int k = 0; k < DI; k += 4) {
        ulonglong2 xm[4], xx[4];
        #pragma unroll
        for (int nn = 0; nn < 4; nn++) {
            xm[nn] = *(const ulonglong2*)(sXm + (nb + nn) * SPAD + k);
            xx[nn] = *(const ulonglong2*)(sXx + (nb + nn) * SPAD + k);
        }
        ulonglong2 wln[4], wrn[4];
        if (k + 4 < DI) {
            #pragma unroll
            for (int jj = 0; jj < 4; jj++) {
                int j = jl + 16 * (jo + jj);
                wln[jj] = *(const ulonglong2*)(sWl + j * SPAD + k + 4);
                wrn[jj] = *(const ulonglong2*)(sWr + j * SPAD + k + 4);
            }
        }
        #pragma unroll
        for (int jj = 0; jj < 4; jj++) {
            #pragma unroll
            for (int nn = 0; nn < 4; nn++) {
                fma2(acc[nn][jj], xm[nn].x, wlc[jj].x);
                fma2(acc[nn][jj], xm[nn].y, wlc[jj].y);
                fma2(acc[nn][jj], xx[nn].x, wrc[jj].x);
                fma2(acc[nn][jj], xx[nn].y, wrc[jj].y);
            }
        }
        if (k + 4 < DI) {
            #pragma unroll
            for (int jj = 0; jj < 4; jj++) { wlc[jj] = wln[jj]; wrc[jj] = wrn[jj]; }
        }
    }

    #pragma unroll
    for (int nn = 0; nn < 4; nn++) {
        int n = node0 + nb + nn;
        if (n < NN) {
            #pragma unroll
            for (int jj = 0; jj < 4; jj++) {
                int j = jl + 16 * (jo + jj);
                float2 s = unpack2(acc[nn][jj]);
                float v = s.x + s.y + bl[j];
                g_h[(size_t)n * DH + j] = fmaxf(v, 0.0f);
            }
        }
    }
}

// ---------------- layer-2 GEMMs (in=128, out=64) ----------------
// FINAL=false: g_p = h @ Wl2^T
// FINAL=true : out = log_softmax(relu(csr_mean(g_p) + bl2 + h @ Wr2^T)), gather fused
template<bool FINAL>
__global__ void __launch_bounds__(256) k_gemmB(
    const float* __restrict__ W, const float* __restrict__ bias, float* __restrict__ out)
{
    extern __shared__ float smem[];
    float* sW   = smem;                 // [64][SPAD]
    float* sX   = sW + DO * SPAD;       // [64][SPAD]
    float* sAgg = sX + 64 * SPAD;       // [64][APAD]  (FINAL only)

    const int tid   = threadIdx.x;
    const int node0 = blockIdx.x * 64;
    const int r     = tid >> 5;
    const int k4    = (tid & 31) * 4;
    const int lane  = tid & 31;

    #pragma unroll
    for (int it = 0; it < 8; it++) {
        int j = it * 8 + r;
        *(float4*)(sW + j * SPAD + k4) = *(const float4*)(W + j * DH + k4);
        int n = node0 + j;
        float4 h4 = make_float4(0.f, 0.f, 0.f, 0.f);
        if (n < NN) h4 = *(const float4*)(g_h + (size_t)n * DH + k4);
        *(float4*)(sX + j * SPAD + k4) = h4;
    }

    if (FINAL) {
        // fused CSR gather: warp w handles nodes node0 + w*8 .. +7, mean of g_p rows
        #pragma unroll
        for (int i = 0; i < 8; i++) {
            int nl = r * 8 + i;
            int n  = node0 + nl;
            float2 a = make_float2(0.f, 0.f);
            int deg = 0;
            if (n < NN) {
                int beg = g_rp[n], end = g_rp[n + 1];
                deg = end - beg;
                int t = beg;
                for (; t + 2 <= end; t += 2) {
                    int s0 = g_srt[t], s1 = g_srt[t + 1];
                    float2 v0 = *(const float2*)(g_p + (size_t)s0 * DO + lane * 2);
                    float2 v1 = *(const float2*)(g_p + (size_t)s1 * DO + lane * 2);
                    a.x += v0.x + v1.x; a.y += v0.y + v1.y;
                }
                if (t < end) {
                    int s0 = g_srt[t];
                    float2 v0 = *(const float2*)(g_p + (size_t)s0 * DO + lane * 2);
                    a.x += v0.x; a.y += v0.y;
                }
            }
            float inv = 1.0f / fmaxf((float)deg, 1.0f);
            *(float2*)(sAgg + nl * APAD + lane * 2) = make_float2(a.x * inv, a.y * inv);
        }
    }
    __syncthreads();

    const int jl = lane & 15;
    const int nb = ((tid >> 5) * 2 + (lane >> 4)) * 4;

    unsigned long long acc[4][4];
    #pragma unroll
    for (int nn = 0; nn < 4; nn++)
        #pragma unroll
        for (int jj = 0; jj < 4; jj++) acc[nn][jj] = 0ull;

    #pragma unroll 4
    for (int k = 0; k < DH; k += 4) {
        ulonglong2 xv[4];
        #pragma unroll
        for (int nn = 0; nn < 4; nn++)
            xv[nn] = *(const ulonglong2*)(sX + (nb + nn) * SPAD + k);
        #pragma unroll
        for (int jj = 0; jj < 4; jj++) {
            int j = jl + 16 * jj;
            ulonglong2 wv = *(const ulonglong2*)(sW + j * SPAD + k);
            #pragma unroll
            for (int nn = 0; nn < 4; nn++) {
                fma2(acc[nn][jj], xv[nn].x, wv.x);
                fma2(acc[nn][jj], xv[nn].y, wv.y);
            }
        }
    }

    #pragma unroll
    for (int nn = 0; nn < 4; nn++) {
        int n = node0 + nb + nn;
        bool valid = (n < NN);
        if (FINAL) {
            int nl = nb + nn;
            float v[4];
            #pragma unroll
            for (int jj = 0; jj < 4; jj++) {
                int j = jl + 16 * jj;
                float2 s = unpack2(acc[nn][jj]);
                float t = s.x + s.y + sAgg[nl * APAD + j] + bias[j];
                v[jj] = fmaxf(t, 0.0f);
            }
            float m = fmaxf(fmaxf(v[0], v[1]), fmaxf(v[2], v[3]));
            #pragma unroll
            for (int o = 8; o > 0; o >>= 1) m = fmaxf(m, __shfl_xor_sync(0xffffffffu, m, o));
            float ss = expf(v[0] - m) + expf(v[1] - m) + expf(v[2] - m) + expf(v[3] - m);
            #pragma unroll
            for (int o = 8; o > 0; o >>= 1) ss += __shfl_xor_sync(0xffffffffu, ss, o);
            float lse = m + logf(ss);
            if (valid) {
                #pragma unroll
                for (int jj = 0; jj < 4; jj++) {
                    int j = jl + 16 * jj;
                    out[(size_t)n * DO + j] = v[jj] - lse;
                }
            }
        } else {
            if (valid) {
                #pragma unroll
                for (int jj = 0; jj < 4; jj++) {
                    int j = jl + 16 * jj;
                    float2 s = unpack2(acc[nn][jj]);
                    g_p[(size_t)n * DO + j] = s.x + s.y;
                }
            }
        }
    }
}

// ---------------- launch ----------------
extern "C" void kernel_launch(void* const* d_in, const int* in_sizes, int n_in,
                              void* d_out, int out_size) {
    const float* x   = (const float*)d_in[0];
    const void*  ei  = d_in[1];
    const float* Wl1 = (const float*)d_in[2];
    const float* bl1 = (const float*)d_in[3];
    const float* Wr1 = (const float*)d_in[4];
    const float* Wl2 = (const float*)d_in[5];
    const float* bl2 = (const float*)d_in[6];
    const float* Wr2 = (const float*)d_in[7];
    float* out = (float*)d_out;

    const int SM1  = (2 * DH * SPAD + 2 * 64 * SPAD) * (int)sizeof(float);   // 202752 B
    const int SM2  = (2 * 64 * SPAD) * (int)sizeof(float);                   // 67584 B
    const int SM2F = SM2 + 64 * APAD * (int)sizeof(float);                   // + mean tile
    (void)cudaFuncSetAttribute(k_gemm1,        cudaFuncAttributeMaxDynamicSharedMemorySize, SM1);
    (void)cudaFuncSetAttribute(k_gemmB<false>, cudaFuncAttributeMaxDynamicSharedMemorySize, SM2);
    (void)cudaFuncSetAttribute(k_gemmB<true>,  cudaFuncAttributeMaxDynamicSharedMemorySize, SM2F);

    const int GN   = (NN + 63) / 64;
    const int NBLK = (NN + 255) / 256;
    const int EB   = (NE + 255) / 256;
    const int GW   = (NN * 32 + 255) / 256;

    k_init<<<NBLK, 256>>>(ei);
    k_hist<<<EB, 256>>>(ei);
    k_scan1<<<NBLK, 256>>>();
    k_scan2<<<1, 256>>>(NBLK);
    k_scan3<<<NBLK, 256>>>();
    k_reorder<<<EB, 256>>>(ei);
    k_gather_x<<<GW, 256>>>(x);
    k_gemm1<<<GN, 512, SM1>>>(x, Wl1, bl1, Wr1);
    k_gemmB<false><<<GN, 256, SM2>>>(Wl2, nullptr, nullptr);
    k_gemmB<true><<<GN, 256, SM2F>>>(Wr2, bl2, out);
}

// round 9
// speedup vs baseline: 1.0853x; 1.0853x over previous
#include <cuda_runtime.h>

#define NN 50000
#define NE 800000
#define DI 128
#define DH 128
#define DO 64
#define SPAD 132   // padded smem row stride (floats)

// Scratch (device globals). 16B-aligned for float4 access.
__device__ __align__(16) float g_agg[NN * DI];   // mean-aggregated features (l1: 128d, l2: first 64d)
__device__ __align__(16) float g_h[NN * DH];     // layer-1 output
__device__ __align__(16) float g_p[NN * DO];     // h @ Wl2^T (pre-aggregation)
__device__ int g_rp[NN + 1];                     // CSR row ptr (by dst)
__device__ int g_cur[NN];                        // degree, then cursor
__device__ int g_srt[NE];                        // src ids sorted by dst
__device__ int g_blksum[256];                    // scan partials
__device__ int g_ei_is32;

// ---------------- packed fp32x2 helpers ----------------
__device__ __forceinline__ void fma2(unsigned long long &d, unsigned long long a, unsigned long long b) {
    asm("fma.rn.f32x2 %0, %1, %2, %0;" : "+l"(d) : "l"(a), "l"(b));
}
__device__ __forceinline__ float2 unpack2(unsigned long long v) {
    float2 r;
    asm("mov.b64 {%0, %1}, %2;" : "=f"(r.x), "=f"(r.y) : "l"(v));
    return r;
}

__device__ __forceinline__ void load_edge(const void* ei, int e, int is32, int& src, int& dst) {
    if (is32) {
        const int* p = (const int*)ei;
        src = p[e]; dst = p[NE + e];
    } else {
        const long long* p = (const long long*)ei;
        src = (int)p[e]; dst = (int)p[NE + e];
    }
}

// ---------------- init: zero degrees + edge-index dtype probe ----------------
__global__ void k_init(const void* ei) {
    int i = blockIdx.x * blockDim.x + threadIdx.x;
    if (i < NN) g_cur[i] = 0;
    if (blockIdx.x == 0 && threadIdx.x == 0) {
        const long long* p = (const long long*)ei;
        int is32 = 0;
        #pragma unroll 8
        for (int t = 0; t < 64; t++) {
            long long v = p[t];
            if (v < 0 || v >= NN) is32 = 1;
        }
        g_ei_is32 = is32;
    }
}

// ---------------- CSR build ----------------
__global__ void k_hist(const void* __restrict__ ei) {
    int e = blockIdx.x * blockDim.x + threadIdx.x;
    if (e >= NE) return;
    int src, dst;
    load_edge(ei, e, g_ei_is32, src, dst);
    if ((unsigned)src < NN && (unsigned)dst < NN) atomicAdd(&g_cur[dst], 1);
}
__global__ void k_scan1() {
    __shared__ int s[256];
    int tid = threadIdx.x;
    int i = blockIdx.x * 256 + tid;
    s[tid] = (i < NN) ? g_cur[i] : 0;
    __syncthreads();
    for (int o = 128; o > 0; o >>= 1) {
        if (tid < o) s[tid] += s[tid + o];
        __syncthreads();
    }
    if (tid == 0) g_blksum[blockIdx.x] = s[0];
}
__global__ void k_scan2(int nblk) {
    __shared__ int s[256];
    int tid = threadIdx.x;
    int v = (tid < nblk) ? g_blksum[tid] : 0;
    s[tid] = v;
    __syncthreads();
    for (int o = 1; o < 256; o <<= 1) {
        int t = (tid >= o) ? s[tid - o] : 0;
        __syncthreads();
        s[tid] += t;
        __syncthreads();
    }
    if (tid < nblk) g_blksum[tid] = s[tid] - v;
}
__global__ void k_scan3() {
    __shared__ int s[256];
    int tid = threadIdx.x;
    int i = blockIdx.x * 256 + tid;
    int v = (i < NN) ? g_cur[i] : 0;
    s[tid] = v;
    __syncthreads();
    for (int o = 1; o < 256; o <<= 1) {
        int t = (tid >= o) ? s[tid - o] : 0;
        __syncthreads();
        s[tid] += t;
        __syncthreads();
    }
    int excl = g_blksum[blockIdx.x] + s[tid] - v;
    if (i < NN) {
        g_rp[i]  = excl;
        g_cur[i] = excl;
        if (i == NN - 1) g_rp[NN] = excl + v;
    }
}
__global__ void k_reorder(const void* __restrict__ ei) {
    int e = blockIdx.x * blockDim.x + threadIdx.x;
    if (e >= NE) return;
    int src, dst;
    load_edge(ei, e, g_ei_is32, src, dst);
    if ((unsigned)src < NN && (unsigned)dst < NN) {
        int pos = atomicAdd(&g_cur[dst], 1);
        if (pos < NE) g_srt[pos] = src;
    }
}

// ---------------- gather (layer 1): mean of x[src] per dst -> g_agg (4-way MLP) ----------------
__global__ void k_gather_x(const float* __restrict__ x) {
    int n    = (blockIdx.x * blockDim.x + threadIdx.x) >> 5;
    int lane = threadIdx.x & 31;
    if (n >= NN) return;
    int beg = g_rp[n], end = g_rp[n + 1];
    float4 a = make_float4(0.f, 0.f, 0.f, 0.f);
    int i = beg;
    for (; i + 4 <= end; i += 4) {
        int s0 = g_srt[i], s1 = g_srt[i + 1], s2 = g_srt[i + 2], s3 = g_srt[i + 3];
        float4 v0 = *(const float4*)(x + (size_t)s0 * DI + lane * 4);
        float4 v1 = *(const float4*)(x + (size_t)s1 * DI + lane * 4);
        float4 v2 = *(const float4*)(x + (size_t)s2 * DI + lane * 4);
        float4 v3 = *(const float4*)(x + (size_t)s3 * DI + lane * 4);
        a.x += (v0.x + v1.x) + (v2.x + v3.x);
        a.y += (v0.y + v1.y) + (v2.y + v3.y);
        a.z += (v0.z + v1.z) + (v2.z + v3.z);
        a.w += (v0.w + v1.w) + (v2.w + v3.w);
    }
    for (; i < end; i++) {
        int s0 = g_srt[i];
        float4 v0 = *(const float4*)(x + (size_t)s0 * DI + lane * 4);
        a.x += v0.x; a.y += v0.y; a.z += v0.z; a.w += v0.w;
    }
    float inv = 1.0f / fmaxf((float)(end - beg), 1.0f);
    *(float4*)(g_agg + (size_t)n * DI + lane * 4) =
        make_float4(a.x * inv, a.y * inv, a.z * inv, a.w * inv);
}

// ---------------- gather (layer 2): mean of g_p[src] per dst -> g_agg (64d, 4-way MLP) ----------------
__global__ void k_gather_p() {
    int n    = (blockIdx.x * blockDim.x + threadIdx.x) >> 5;
    int lane = threadIdx.x & 31;
    if (n >= NN) return;
    int beg = g_rp[n], end = g_rp[n + 1];
    float2 a = make_float2(0.f, 0.f);
    int i = beg;
    for (; i + 4 <= end; i += 4) {
        int s0 = g_srt[i], s1 = g_srt[i + 1], s2 = g_srt[i + 2], s3 = g_srt[i + 3];
        float2 v0 = *(const float2*)(g_p + (size_t)s0 * DO + lane * 2);
        float2 v1 = *(const float2*)(g_p + (size_t)s1 * DO + lane * 2);
        float2 v2 = *(const float2*)(g_p + (size_t)s2 * DO + lane * 2);
        float2 v3 = *(const float2*)(g_p + (size_t)s3 * DO + lane * 2);
        a.x += (v0.x + v1.x) + (v2.x + v3.x);
        a.y += (v0.y + v1.y) + (v2.y + v3.y);
    }
    for (; i < end; i++) {
        int s0 = g_srt[i];
        float2 v0 = *(const float2*)(g_p + (size_t)s0 * DO + lane * 2);
        a.x += v0.x; a.y += v0.y;
    }
    float inv = 1.0f / fmaxf((float)(end - beg), 1.0f);
    *(float2*)(g_agg + (size_t)n * DO + lane * 2) = make_float2(a.x * inv, a.y * inv);
}

// ---------------- layer-1 fused GEMM: h = relu(mean @ Wl1^T + bl1 + x @ Wr1^T) ----------------
__global__ void __launch_bounds__(512, 1) k_gemm1(
    const float* __restrict__ x, const float* __restrict__ Wl,
    const float* __restrict__ bl, const float* __restrict__ Wr)
{
    extern __shared__ float smem[];
    float* sWl = smem;                  // [128][SPAD]
    float* sWr = sWl + DH * SPAD;       // [128][SPAD]
    float* sXm = sWr + DH * SPAD;       // [64][SPAD]
    float* sXx = sXm + 64 * SPAD;       // [64][SPAD]

    const int tid   = threadIdx.x;
    const int node0 = blockIdx.x * 64;
    const int r     = tid >> 5;
    const int k4    = (tid & 31) * 4;

    #pragma unroll
    for (int it = 0; it < 8; it++) {
        int j = it * 16 + r;
        *(float4*)(sWl + j * SPAD + k4) = *(const float4*)(Wl + j * DI + k4);
        *(float4*)(sWr + j * SPAD + k4) = *(const float4*)(Wr + j * DI + k4);
    }
    #pragma unroll
    for (int it = 0; it < 4; it++) {
        int nl = it * 16 + r;
        int n  = node0 + nl;
        float4 xm = make_float4(0.f, 0.f, 0.f, 0.f), xx = xm;
        if (n < NN) {
            xm = *(const float4*)(g_agg + (size_t)n * DI + k4);   // already the mean
            xx = *(const float4*)(x + (size_t)n * DI + k4);
        }
        *(float4*)(sXm + nl * SPAD + k4) = xm;
        *(float4*)(sXx + nl * SPAD + k4) = xx;
    }
    __syncthreads();

    const int lane = tid & 31;
    const int jl   = lane & 15;
    const int jo   = (r >> 3) * 4;
    const int nb   = ((r & 7) * 2 + (lane >> 4)) * 4;

    unsigned long long acc[4][4];
    #pragma unroll
    for (int nn = 0; nn < 4; nn++)
        #pragma unroll
        for (int jj = 0; jj < 4; jj++) acc[nn][jj] = 0ull;

    #pragma unroll 4
    for (int k = 0; k < DI; k += 4) {
        ulonglong2 xm[4], xx[4];
        #pragma unroll
        for (int nn = 0; nn < 4; nn++) {
            xm[nn] = *(const ulonglong2*)(sXm + (nb + nn) * SPAD + k);
            xx[nn] = *(const ulonglong2*)(sXx + (nb + nn) * SPAD + k);
        }
        #pragma unroll
        for (int jj = 0; jj < 4; jj++) {
            int j = jl + 16 * (jo + jj);
            ulonglong2 wl = *(const ulonglong2*)(sWl + j * SPAD + k);
            ulonglong2 wr = *(const ulonglong2*)(sWr + j * SPAD + k);
            #pragma unroll
            for (int nn = 0; nn < 4; nn++) {
                fma2(acc[nn][jj], xm[nn].x, wl.x);
                fma2(acc[nn][jj], xm[nn].y, wl.y);
                fma2(acc[nn][jj], xx[nn].x, wr.x);
                fma2(acc[nn][jj], xx[nn].y, wr.y);
            }
        }
    }

    #pragma unroll
    for (int nn = 0; nn < 4; nn++) {
        int n = node0 + nb + nn;
        if (n < NN) {
            #pragma unroll
            for (int jj = 0; jj < 4; jj++) {
                int j = jl + 16 * (jo + jj);
                float2 s = unpack2(acc[nn][jj]);
                float v = s.x + s.y + bl[j];
                g_h[(size_t)n * DH + j] = fmaxf(v, 0.0f);
            }
        }
    }
}

// ---------------- layer-2 GEMMs (in=128, out=64) ----------------
// FINAL=false: g_p = h @ Wl2^T
// FINAL=true : out = log_softmax(relu(mean_agg + bl2 + h @ Wr2^T))  (lsm fused)
template<bool FINAL>
__global__ void __launch_bounds__(256) k_gemmB(
    const float* __restrict__ W, const float* __restrict__ bias, float* __restrict__ out)
{
    extern __shared__ float smem[];
    float* sW = smem;                 // [64][SPAD]
    float* sX = sW + DO * SPAD;       // [64][SPAD]

    const int tid   = threadIdx.x;
    const int node0 = blockIdx.x * 64;
    const int r     = tid >> 5;
    const int k4    = (tid & 31) * 4;

    #pragma unroll
    for (int it = 0; it < 8; it++) {
        int j = it * 8 + r;
        *(float4*)(sW + j * SPAD + k4) = *(const float4*)(W + j * DH + k4);
        int n = node0 + j;
        float4 h4 = make_float4(0.f, 0.f, 0.f, 0.f);
        if (n < NN) h4 = *(const float4*)(g_h + (size_t)n * DH + k4);
        *(float4*)(sX + j * SPAD + k4) = h4;
    }
    __syncthreads();

    const int lane = tid & 31;
    const int jl   = lane & 15;
    const int nb   = ((tid >> 5) * 2 + (lane >> 4)) * 4;

    unsigned long long acc[4][4];
    #pragma unroll
    for (int nn = 0; nn < 4; nn++)
        #pragma unroll
        for (int jj = 0; jj < 4; jj++) acc[nn][jj] = 0ull;

    #pragma unroll 4
    for (int k = 0; k < DH; k += 4) {
        ulonglong2 xv[4];
        #pragma unroll
        for (int nn = 0; nn < 4; nn++)
            xv[nn] = *(const ulonglong2*)(sX + (nb + nn) * SPAD + k);
        #pragma unroll
        for (int jj = 0; jj < 4; jj++) {
            int j = jl + 16 * jj;
            ulonglong2 wv = *(const ulonglong2*)(sW + j * SPAD + k);
            #pragma unroll
            for (int nn = 0; nn < 4; nn++) {
                fma2(acc[nn][jj], xv[nn].x, wv.x);
                fma2(acc[nn][jj], xv[nn].y, wv.y);
            }
        }
    }

    #pragma unroll
    for (int nn = 0; nn < 4; nn++) {
        int n = node0 + nb + nn;
        bool valid = (n < NN);
        if (FINAL) {
            float v[4];
            #pragma unroll
            for (int jj = 0; jj < 4; jj++) {
                int j = jl + 16 * jj;
                float2 s = unpack2(acc[nn][jj]);
                float t = s.x + s.y;
                if (valid) t += g_agg[(size_t)n * DO + j] + bias[j];   // g_agg holds the mean
                v[jj] = valid ? fmaxf(t, 0.0f) : 0.0f;
            }
            float m = fmaxf(fmaxf(v[0], v[1]), fmaxf(v[2], v[3]));
            #pragma unroll
            for (int o = 8; o > 0; o >>= 1) m = fmaxf(m, __shfl_xor_sync(0xffffffffu, m, o));
            float ss = expf(v[0] - m) + expf(v[1] - m) + expf(v[2] - m) + expf(v[3] - m);
            #pragma unroll
            for (int o = 8; o > 0; o >>= 1) ss += __shfl_xor_sync(0xffffffffu, ss, o);
            float lse = m + logf(ss);
            if (valid) {
                #pragma unroll
                for (int jj = 0; jj < 4; jj++) {
                    int j = jl + 16 * jj;
                    out[(size_t)n * DO + j] = v[jj] - lse;
                }
            }
        } else {
            if (valid) {
                #pragma unroll
                for (int jj = 0; jj < 4; jj++) {
                    int j = jl + 16 * jj;
                    float2 s = unpack2(acc[nn][jj]);
                    g_p[(size_t)n * DO + j] = s.x + s.y;
                }
            }
        }
    }
}

// ---------------- launch ----------------
extern "C" void kernel_launch(void* const* d_in, const int* in_sizes, int n_in,
                              void* d_out, int out_size) {
    const float* x   = (const float*)d_in[0];
    const void*  ei  = d_in[1];
    const float* Wl1 = (const float*)d_in[2];
    const float* bl1 = (const float*)d_in[3];
    const float* Wr1 = (const float*)d_in[4];
    const float* Wl2 = (const float*)d_in[5];
    const float* bl2 = (const float*)d_in[6];
    const float* Wr2 = (const float*)d_in[7];
    float* out = (float*)d_out;

    const int SM1 = (2 * DH * SPAD + 2 * 64 * SPAD) * (int)sizeof(float);  // 202752 B
    const int SM2 = (2 * 64 * SPAD) * (int)sizeof(float);                  // 67584 B
    (void)cudaFuncSetAttribute(k_gemm1,        cudaFuncAttributeMaxDynamicSharedMemorySize, SM1);
    (void)cudaFuncSetAttribute(k_gemmB<false>, cudaFuncAttributeMaxDynamicSharedMemorySize, SM2);
    (void)cudaFuncSetAttribute(k_gemmB<true>,  cudaFuncAttributeMaxDynamicSharedMemorySize, SM2);

    const int GN   = (NN + 63) / 64;
    const int NBLK = (NN + 255) / 256;
    const int EB   = (NE + 255) / 256;
    const int GW   = (NN * 32 + 255) / 256;

    k_init<<<NBLK, 256>>>(ei);
    k_hist<<<EB, 256>>>(ei);
    k_scan1<<<NBLK, 256>>>();
    k_scan2<<<1, 256>>>(NBLK);
    k_scan3<<<NBLK, 256>>>();
    k_reorder<<<EB, 256>>>(ei);
    k_gather_x<<<GW, 256>>>(x);
    k_gemm1<<<GN, 512, SM1>>>(x, Wl1, bl1, Wr1);
    k_gemmB<false><<<GN, 256, SM2>>>(Wl2, nullptr, nullptr);
    k_gather_p<<<GW, 256>>>();
    k_gemmB<true><<<GN, 256, SM2>>>(Wr2, bl2, out);
}

// round 12
// speedup vs baseline: 1.3109x; 1.2079x over previous
#include <cuda_runtime.h>
#include <cuda_bf16.h>
#include <cstdint>

#define NN 50000
#define NE 800000
#define DI 128
#define DH 128
#define DO 64
#define SPAD 132   // padded smem row stride (floats) for SIMT gemmB

// ---- mma.sync gemm1 constants ----
#define KS2 136                        // bf16 smem row stride (272B: 16B-mult, LDSM conflict-free)
#define OFF_AHI 0
#define OFF_ALO (128 * KS2 * 2)        // 34816
#define OFF_BHI (2 * 128 * KS2 * 2)    // 69632
#define OFF_BLO (3 * 128 * KS2 * 2)    // 104448
#define OFF_BIAS (4 * 128 * KS2 * 2)   // 139264
#define SM_MMA_TOTAL (OFF_BIAS + 512)  // 139776

// Scratch (device globals). 16B-aligned for float4 access.
__device__ __align__(16) float g_agg[NN * DI];
__device__ __align__(16) float g_h[NN * DH];
__device__ __align__(16) float g_p[NN * DO];
__device__ int g_rp[NN + 1];
__device__ int g_cur[NN];
__device__ int g_srt[NE];
__device__ int g_blksum[256];
__device__ int g_ei_is32;

// ---------------- packed fp32x2 helpers (SIMT gemmB) ----------------
__device__ __forceinline__ void fma2(unsigned long long &d, unsigned long long a, unsigned long long b) {
    asm("fma.rn.f32x2 %0, %1, %2, %0;" : "+l"(d) : "l"(a), "l"(b));
}
__device__ __forceinline__ float2 unpack2(unsigned long long v) {
    float2 r;
    asm("mov.b64 {%0, %1}, %2;" : "=f"(r.x), "=f"(r.y) : "l"(v));
    return r;
}

__device__ __forceinline__ void load_edge(const void* ei, int e, int is32, int& src, int& dst) {
    if (is32) {
        const int* p = (const int*)ei;
        src = p[e]; dst = p[NE + e];
    } else {
        const long long* p = (const long long*)ei;
        src = (int)p[e]; dst = (int)p[NE + e];
    }
}

// ---------------- init + CSR build ----------------
__global__ void k_init(const void* ei) {
    int i = blockIdx.x * blockDim.x + threadIdx.x;
    if (i < NN) g_cur[i] = 0;
    if (blockIdx.x == 0 && threadIdx.x == 0) {
        const long long* p = (const long long*)ei;
        int is32 = 0;
        for (int t = 0; t < 64; t++) {
            long long v = p[t];
            if (v < 0 || v >= NN) is32 = 1;
        }
        g_ei_is32 = is32;
    }
}
__global__ void k_hist(const void* __restrict__ ei) {
    int e = blockIdx.x * blockDim.x + threadIdx.x;
    if (e >= NE) return;
    int src, dst;
    load_edge(ei, e, g_ei_is32, src, dst);
    if ((unsigned)src < NN && (unsigned)dst < NN) atomicAdd(&g_cur[dst], 1);
}
__global__ void k_scan1() {
    __shared__ int s[256];
    int tid = threadIdx.x;
    int i = blockIdx.x * 256 + tid;
    s[tid] = (i < NN) ? g_cur[i] : 0;
    __syncthreads();
    for (int o = 128; o > 0; o >>= 1) {
        if (tid < o) s[tid] += s[tid + o];
        __syncthreads();
    }
    if (tid == 0) g_blksum[blockIdx.x] = s[0];
}
__global__ void k_scan2(int nblk) {
    __shared__ int s[256];
    int tid = threadIdx.x;
    int v = (tid < nblk) ? g_blksum[tid] : 0;
    s[tid] = v;
    __syncthreads();
    for (int o = 1; o < 256; o <<= 1) {
        int t = (tid >= o) ? s[tid - o] : 0;
        __syncthreads();
        s[tid] += t;
        __syncthreads();
    }
    if (tid < nblk) g_blksum[tid] = s[tid] - v;
}
__global__ void k_scan3() {
    __shared__ int s[256];
    int tid = threadIdx.x;
    int i = blockIdx.x * 256 + tid;
    int v = (i < NN) ? g_cur[i] : 0;
    s[tid] = v;
    __syncthreads();
    for (int o = 1; o < 256; o <<= 1) {
        int t = (tid >= o) ? s[tid - o] : 0;
        __syncthreads();
        s[tid] += t;
        __syncthreads();
    }
    int excl = g_blksum[blockIdx.x] + s[tid] - v;
    if (i < NN) {
        g_rp[i]  = excl;
        g_cur[i] = excl;
        if (i == NN - 1) g_rp[NN] = excl + v;
    }
}
__global__ void k_reorder(const void* __restrict__ ei) {
    int e = blockIdx.x * blockDim.x + threadIdx.x;
    if (e >= NE) return;
    int src, dst;
    load_edge(ei, e, g_ei_is32, src, dst);
    if ((unsigned)src < NN && (unsigned)dst < NN) {
        int pos = atomicAdd(&g_cur[dst], 1);
        if (pos < NE) g_srt[pos] = src;
    }
}

// ---------------- gather (layer 1): mean of x[src] per dst -> g_agg ----------------
__global__ void k_gather_x(const float* __restrict__ x) {
    int n    = (blockIdx.x * blockDim.x + threadIdx.x) >> 5;
    int lane = threadIdx.x & 31;
    if (n >= NN) return;
    int beg = g_rp[n], end = g_rp[n + 1];
    float4 a = make_float4(0.f, 0.f, 0.f, 0.f);
    int i = beg;
    for (; i + 2 <= end; i += 2) {
        int s0 = g_srt[i], s1 = g_srt[i + 1];
        float4 v0 = *(const float4*)(x + (size_t)s0 * DI + lane * 4);
        float4 v1 = *(const float4*)(x + (size_t)s1 * DI + lane * 4);
        a.x += v0.x + v1.x; a.y += v0.y + v1.y;
        a.z += v0.z + v1.z; a.w += v0.w + v1.w;
    }
    if (i < end) {
        int s0 = g_srt[i];
        float4 v0 = *(const float4*)(x + (size_t)s0 * DI + lane * 4);
        a.x += v0.x; a.y += v0.y; a.z += v0.z; a.w += v0.w;
    }
    float inv = 1.0f / fmaxf((float)(end - beg), 1.0f);
    *(float4*)(g_agg + (size_t)n * DI + lane * 4) =
        make_float4(a.x * inv, a.y * inv, a.z * inv, a.w * inv);
}

// ---------------- gather (layer 2): mean of g_p[src] per dst -> g_agg (64d) ----------------
__global__ void k_gather_p() {
    int n    = (blockIdx.x * blockDim.x + threadIdx.x) >> 5;
    int lane = threadIdx.x & 31;
    if (n >= NN) return;
    int beg = g_rp[n], end = g_rp[n + 1];
    float2 a = make_float2(0.f, 0.f);
    int i = beg;
    for (; i + 2 <= end; i += 2) {
        int s0 = g_srt[i], s1 = g_srt[i + 1];
        float2 v0 = *(const float2*)(g_p + (size_t)s0 * DO + lane * 2);
        float2 v1 = *(const float2*)(g_p + (size_t)s1 * DO + lane * 2);
        a.x += v0.x + v1.x; a.y += v0.y + v1.y;
    }
    if (i < end) {
        int s0 = g_srt[i];
        float2 v0 = *(const float2*)(g_p + (size_t)s0 * DO + lane * 2);
        a.x += v0.x; a.y += v0.y;
    }
    float inv = 1.0f / fmaxf((float)(end - beg), 1.0f);
    *(float2*)(g_agg + (size_t)n * DO + lane * 2) = make_float2(a.x * inv, a.y * inv);
}

// ================= mma.sync helpers =================
__device__ __forceinline__ uint32_t smem_u32(const void* p) {
    uint32_t a;
    asm("{ .reg .u64 t; cvta.to.shared.u64 t, %1; cvt.u32.u64 %0, t; }" : "=r"(a) : "l"(p));
    return a;
}
__device__ __forceinline__ void ldsm4(uint32_t& r0, uint32_t& r1, uint32_t& r2, uint32_t& r3,
                                      uint32_t addr) {
    asm volatile("ldmatrix.sync.aligned.m8n8.x4.shared.b16 {%0,%1,%2,%3}, [%4];"
                 : "=r"(r0), "=r"(r1), "=r"(r2), "=r"(r3) : "r"(addr));
}
__device__ __forceinline__ void mma_bf16(float* d, uint32_t a0, uint32_t a1, uint32_t a2,
                                         uint32_t a3, uint32_t b0, uint32_t b1) {
    asm volatile(
        "mma.sync.aligned.m16n8k16.row.col.f32.bf16.bf16.f32 "
        "{%0,%1,%2,%3}, {%4,%5,%6,%7}, {%8,%9}, {%0,%1,%2,%3};"
        : "+f"(d[0]), "+f"(d[1]), "+f"(d[2]), "+f"(d[3])
        : "r"(a0), "r"(a1), "r"(a2), "r"(a3), "r"(b0), "r"(b1));
}
// stage 64 cols of one fp32 row as bf16 hi/lo into padded smem (stride KS2)
__device__ __forceinline__ void stage_half_row(const float* __restrict__ src,
                                               char* hi, char* lo,
                                               int row, int col0, bool valid) {
    uint32_t base = (uint32_t)(row * KS2 + col0) * 2u;
    #pragma unroll
    for (int q = 0; q < 16; q++) {
        float4 v = valid ? *(const float4*)(src + col0 + 4 * q)
                         : make_float4(0.f, 0.f, 0.f, 0.f);
        __nv_bfloat16 h0 = __float2bfloat16(v.x), h1 = __float2bfloat16(v.y);
        __nv_bfloat16 h2 = __float2bfloat16(v.z), h3 = __float2bfloat16(v.w);
        __nv_bfloat16 l0 = __float2bfloat16(v.x - __bfloat162float(h0));
        __nv_bfloat16 l1 = __float2bfloat16(v.y - __bfloat162float(h1));
        __nv_bfloat16 l2 = __float2bfloat16(v.z - __bfloat162float(h2));
        __nv_bfloat16 l3 = __float2bfloat16(v.w - __bfloat162float(h3));
        uint2 hp, lp;
        hp.x = ((uint32_t)__bfloat16_as_ushort(h1) << 16) | __bfloat16_as_ushort(h0);
        hp.y = ((uint32_t)__bfloat16_as_ushort(h3) << 16) | __bfloat16_as_ushort(h2);
        lp.x = ((uint32_t)__bfloat16_as_ushort(l1) << 16) | __bfloat16_as_ushort(l0);
        lp.y = ((uint32_t)__bfloat16_as_ushort(l3) << 16) | __bfloat16_as_ushort(l2);
        *(uint2*)(hi + base + 8u * q) = hp;
        *(uint2*)(lo + base + 8u * q) = lp;
    }
}

// ---------------- layer-1 GEMM via mma.sync (split-bf16, 3 products) ----------------
// h[128 nodes][128] = relu(mean @ Wl^T + x @ Wr^T + bl); 256 thr, warp tile 32x64.
__global__ void __launch_bounds__(256, 1) k_gemm1_mma(
    const float* __restrict__ x, const float* __restrict__ Wl,
    const float* __restrict__ bl, const float* __restrict__ Wr)
{
    extern __shared__ char smem[];
    const uint32_t sb = smem_u32(smem);
    const int tid  = threadIdx.x;
    const int warp = tid >> 5, lane = tid & 31;
    const int node0 = blockIdx.x * 128;

    if (tid < 128) ((float*)(smem + OFF_BIAS))[tid] = bl[tid];

    const int wm = (warp & 3) * 32;       // warp m-base (nodes)
    const int wn = (warp >> 2) * 64;      // warp n-base (outputs)

    float acc[2][8][4];
    #pragma unroll
    for (int mt = 0; mt < 2; mt++)
        #pragma unroll
        for (int nt = 0; nt < 8; nt++)
            #pragma unroll
            for (int q = 0; q < 4; q++) acc[mt][nt][q] = 0.f;

    // lane-dependent LDSM address components (element offsets within a tile)
    const uint32_t aRow = (uint32_t)(lane & 15);            // + m0
    const uint32_t aCol = (uint32_t)((lane >> 4) << 3);     // + kb
    const uint32_t bRow = (uint32_t)(((lane >> 4) << 3) + (lane & 7));   // + n0
    const uint32_t bCol = (uint32_t)(((lane >> 3) & 1) << 3);            // + kb

    #pragma unroll
    for (int phase = 0; phase < 2; phase++) {
        // ---- stage A (nodes) and B (weights) as bf16 hi/lo ----
        {
            int row  = tid >> 1;
            int col0 = (tid & 1) * 64;
            const float* arow = (phase == 0) ? (g_agg + (size_t)(node0 + row) * DI)
                                             : (x + (size_t)(node0 + row) * DI);
            const float* brow = ((phase == 0) ? Wl : Wr) + (size_t)row * DI;
            bool valid = (node0 + row) < NN;
            stage_half_row(arow, smem + OFF_AHI, smem + OFF_ALO, row, col0, valid);
            stage_half_row(brow, smem + OFF_BHI, smem + OFF_BLO, row, col0, true);
        }
        __syncthreads();

        #pragma unroll
        for (int kb = 0; kb < DI; kb += 16) {
            uint32_t ah[2][4], al[2][4];
            #pragma unroll
            for (int mt = 0; mt < 2; mt++) {
                uint32_t eoff = ((uint32_t)(wm + mt * 16) + aRow) * KS2 + (uint32_t)kb + aCol;
                ldsm4(ah[mt][0], ah[mt][1], ah[mt][2], ah[mt][3], sb + OFF_AHI + eoff * 2u);
                ldsm4(al[mt][0], al[mt][1], al[mt][2], al[mt][3], sb + OFF_ALO + eoff * 2u);
            }
            #pragma unroll
            for (int np = 0; np < 4; np++) {
                uint32_t eoff = ((uint32_t)(wn + np * 16) + bRow) * KS2 + (uint32_t)kb + bCol;
                uint32_t bh[4], blq[4];
                ldsm4(bh[0], bh[1], bh[2], bh[3], sb + OFF_BHI + eoff * 2u);
                ldsm4(blq[0], blq[1], blq[2], blq[3], sb + OFF_BLO + eoff * 2u);
                #pragma unroll
                for (int mt = 0; mt < 2; mt++) {
                    mma_bf16(acc[mt][np*2],   ah[mt][0], ah[mt][1], ah[mt][2], ah[mt][3], bh[0],  bh[1]);
                    mma_bf16(acc[mt][np*2+1], ah[mt][0], ah[mt][1], ah[mt][2], ah[mt][3], bh[2],  bh[3]);
                    mma_bf16(acc[mt][np*2],   ah[mt][0], ah[mt][1], ah[mt][2], ah[mt][3], blq[0], blq[1]);
                    mma_bf16(acc[mt][np*2+1], ah[mt][0], ah[mt][1], ah[mt][2], ah[mt][3], blq[2], blq[3]);
                    mma_bf16(acc[mt][np*2],   al[mt][0], al[mt][1], al[mt][2], al[mt][3], bh[0],  bh[1]);
                    mma_bf16(acc[mt][np*2+1], al[mt][0], al[mt][1], al[mt][2], al[mt][3], bh[2],  bh[3]);
                }
            }
        }
        __syncthreads();   // before next phase overwrites smem
    }

    // ---- epilogue: bias + relu, direct stores ----
    const float* sBias = (const float*)(smem + OFF_BIAS);
    #pragma unroll
    for (int mt = 0; mt < 2; mt++) {
        #pragma unroll
        for (int nt = 0; nt < 8; nt++) {
            int gn = wn + nt * 8 + (lane & 3) * 2;
            float b0 = sBias[gn], b1 = sBias[gn + 1];
            int gm0 = node0 + wm + mt * 16 + (lane >> 2);
            if (gm0 < NN) {
                float2 v = make_float2(fmaxf(acc[mt][nt][0] + b0, 0.f),
                                       fmaxf(acc[mt][nt][1] + b1, 0.f));
                *(float2*)(g_h + (size_t)gm0 * DH + gn) = v;
            }
            int gm1 = gm0 + 8;
            if (gm1 < NN) {
                float2 v = make_float2(fmaxf(acc[mt][nt][2] + b0, 0.f),
                                       fmaxf(acc[mt][nt][3] + b1, 0.f));
                *(float2*)(g_h + (size_t)gm1 * DH + gn) = v;
            }
        }
    }
}

// ---------------- layer-2 GEMMs (SIMT, in=128, out=64) ----------------
template<bool FINAL>
__global__ void __launch_bounds__(256) k_gemmB(
    const float* __restrict__ W, const float* __restrict__ bias, float* __restrict__ out)
{
    extern __shared__ float smemf[];
    float* sW = smemf;                 // [64][SPAD]
    float* sX = sW + DO * SPAD;        // [64][SPAD]

    const int tid   = threadIdx.x;
    const int node0 = blockIdx.x * 64;
    const int r     = tid >> 5;
    const int k4    = (tid & 31) * 4;

    #pragma unroll
    for (int it = 0; it < 8; it++) {
        int j = it * 8 + r;
        *(float4*)(sW + j * SPAD + k4) = *(const float4*)(W + j * DH + k4);
        int n = node0 + j;
        float4 h4 = make_float4(0.f, 0.f, 0.f, 0.f);
        if (n < NN) h4 = *(const float4*)(g_h + (size_t)n * DH + k4);
        *(float4*)(sX + j * SPAD + k4) = h4;
    }
    __syncthreads();

    const int lane = tid & 31;
    const int jl   = lane & 15;
    const int nb   = ((tid >> 5) * 2 + (lane >> 4)) * 4;

    unsigned long long acc[4][4];
    #pragma unroll
    for (int nn = 0; nn < 4; nn++)
        #pragma unroll
        for (int jj = 0; jj < 4; jj++) acc[nn][jj] = 0ull;

    #pragma unroll 4
    for (int k = 0; k < DH; k += 4) {
        ulonglong2 xv[4];
        #pragma unroll
        for (int nn = 0; nn < 4; nn++)
            xv[nn] = *(const ulonglong2*)(sX + (nb + nn) * SPAD + k);
        #pragma unroll
        for (int jj = 0; jj < 4; jj++) {
            int j = jl + 16 * jj;
            ulonglong2 wv = *(const ulonglong2*)(sW + j * SPAD + k);
            #pragma unroll
            for (int nn = 0; nn < 4; nn++) {
                fma2(acc[nn][jj], xv[nn].x, wv.x);
                fma2(acc[nn][jj], xv[nn].y, wv.y);
            }
        }
    }

    #pragma unroll
    for (int nn = 0; nn < 4; nn++) {
        int n = node0 + nb + nn;
        bool valid = (n < NN);
        if (FINAL) {
            float v[4];
            #pragma unroll
            for (int jj = 0; jj < 4; jj++) {
                int j = jl + 16 * jj;
                float2 s = unpack2(acc[nn][jj]);
                float t = s.x + s.y;
                if (valid) t += g_agg[(size_t)n * DO + j] + bias[j];
                v[jj] = valid ? fmaxf(t, 0.0f) : 0.0f;
            }
            float m = fmaxf(fmaxf(v[0], v[1]), fmaxf(v[2], v[3]));
            #pragma unroll
            for (int o = 8; o > 0; o >>= 1) m = fmaxf(m, __shfl_xor_sync(0xffffffffu, m, o));
            float ss = expf(v[0] - m) + expf(v[1] - m) + expf(v[2] - m) + expf(v[3] - m);
            #pragma unroll
            for (int o = 8; o > 0; o >>= 1) ss += __shfl_xor_sync(0xffffffffu, ss, o);
            float lse = m + logf(ss);
            if (valid) {
                #pragma unroll
                for (int jj = 0; jj < 4; jj++) {
                    int j = jl + 16 * jj;
                    out[(size_t)n * DO + j] = v[jj] - lse;
                }
            }
        } else {
            if (valid) {
                #pragma unroll
                for (int jj = 0; jj < 4; jj++) {
                    int j = jl + 16 * jj;
                    float2 s = unpack2(acc[nn][jj]);
                    g_p[(size_t)n * DO + j] = s.x + s.y;
                }
            }
        }
    }
}

// ---------------- launch ----------------
extern "C" void kernel_launch(void* const* d_in, const int* in_sizes, int n_in,
                              void* d_out, int out_size) {
    const float* x   = (const float*)d_in[0];
    const void*  ei  = d_in[1];
    const float* Wl1 = (const float*)d_in[2];
    const float* bl1 = (const float*)d_in[3];
    const float* Wr1 = (const float*)d_in[4];
    const float* Wl2 = (const float*)d_in[5];
    const float* bl2 = (const float*)d_in[6];
    const float* Wr2 = (const float*)d_in[7];
    float* out = (float*)d_out;

    const int SM2 = (2 * 64 * SPAD) * (int)sizeof(float);                  // 67584 B
    (void)cudaFuncSetAttribute(k_gemm1_mma,    cudaFuncAttributeMaxDynamicSharedMemorySize, SM_MMA_TOTAL);
    (void)cudaFuncSetAttribute(k_gemmB<false>, cudaFuncAttributeMaxDynamicSharedMemorySize, SM2);
    (void)cudaFuncSetAttribute(k_gemmB<true>,  cudaFuncAttributeMaxDynamicSharedMemorySize, SM2);

    const int GN   = (NN + 63) / 64;
    const int GT   = (NN + 127) / 128;   // 391
    const int NBLK = (NN + 255) / 256;
    const int EB   = (NE + 255) / 256;
    const int GW   = (NN * 32 + 255) / 256;

    k_init<<<NBLK, 256>>>(ei);
    k_hist<<<EB, 256>>>(ei);
    k_scan1<<<NBLK, 256>>>();
    k_scan2<<<1, 256>>>(NBLK);
    k_scan3<<<NBLK, 256>>>();
    k_reorder<<<EB, 256>>>(ei);
    k_gather_x<<<GW, 256>>>(x);
    k_gemm1_mma<<<GT, 256, SM_MMA_TOTAL>>>(x, Wl1, bl1, Wr1);
    k_gemmB<false><<<GN, 256, SM2>>>(Wl2, nullptr, nullptr);
    k_gather_p<<<GW, 256>>>();
    k_gemmB<true><<<GN, 256, SM2>>>(Wr2, bl2, out);
}